// round 2
// baseline (speedup 1.0000x reference)
#include <cuda_runtime.h>
#include <math.h>
#include <float.h>

// Problem constants
#define Bb 8
#define Tt 256
#define NPOS (Bb*Tt)     // 2048
#define IDIM 80          // = ODIM
#define HDIM 256
#define CDIM 64
#define NIT 4
#define TPB 256
#define NSHIFT 159       // alignment shifts
#define NSENC 81         // encoder shifts
#define ETH_I 40         // ETH = 40.0, move is an integer

__device__ float g_partial[NPOS];

// ---------------- reductions (deterministic) ----------------
__device__ __forceinline__ float warpSum(float v) {
#pragma unroll
    for (int o = 16; o > 0; o >>= 1) v += __shfl_down_sync(0xffffffffu, v, o);
    return v;
}

__device__ __forceinline__ float blockSum(float v, float* buf) {
    v = warpSum(v);
    int w = threadIdx.x >> 5, l = threadIdx.x & 31;
    if (l == 0) buf[w] = v;
    __syncthreads();
    if (threadIdx.x == 0) {
        float s = 0.f;
#pragma unroll
        for (int i = 0; i < 8; i++) s += buf[i];
        buf[0] = s;
    }
    __syncthreads();
    float r = buf[0];
    __syncthreads();
    return r;
}

__device__ __forceinline__ float blockMax(float v, float* buf) {
#pragma unroll
    for (int o = 16; o > 0; o >>= 1) v = fmaxf(v, __shfl_down_sync(0xffffffffu, v, o));
    int w = threadIdx.x >> 5, l = threadIdx.x & 31;
    if (l == 0) buf[w] = v;
    __syncthreads();
    if (threadIdx.x == 0) {
        float s = buf[0];
#pragma unroll
        for (int i = 1; i < 8; i++) s = fmaxf(s, buf[i]);
        buf[0] = s;
    }
    __syncthreads();
    float r = buf[0];
    __syncthreads();
    return r;
}

// argmax with first-index tie-break (matches jnp.argmax / lax.top_k ordering)
__device__ __forceinline__ int blockArgmax(const float* arr, int L, float* fb, int* ib) {
    float bv = -FLT_MAX; int bi = 0x7FFFFFFF;
    for (int i = threadIdx.x; i < L; i += TPB) {
        float v = arr[i];
        if (v > bv || (v == bv && i < bi)) { bv = v; bi = i; }
    }
#pragma unroll
    for (int o = 16; o > 0; o >>= 1) {
        float ov = __shfl_down_sync(0xffffffffu, bv, o);
        int   oi = __shfl_down_sync(0xffffffffu, bi, o);
        if (ov > bv || (ov == bv && oi < bi)) { bv = ov; bi = oi; }
    }
    int w = threadIdx.x >> 5, l = threadIdx.x & 31;
    if (l == 0) { fb[w] = bv; ib[w] = bi; }
    __syncthreads();
    if (threadIdx.x == 0) {
        float v = fb[0]; int j = ib[0];
#pragma unroll
        for (int i = 1; i < 8; i++) {
            if (fb[i] > v || (fb[i] == v && ib[i] < j)) { v = fb[i]; j = ib[i]; }
        }
        ib[0] = j;
    }
    __syncthreads();
    int r = ib[0];
    __syncthreads();
    return r;
}

// ---------------- alignment (sim_argmax + y_al extraction) ----------------
// x_aug[s][w] = src[s+w-79] (0 if OOB);  sim[s] = <x_aug[s],y>/(|x_aug[s]|*|y| + 1e-6)
__device__ __forceinline__ int align_fn(const float* src, const float* yr, float ny,
                                        float* sim, float* yal, float* fb, int* ib) {
    int s = threadIdx.x;
    if (s < NSHIFT) {
        int wlo = 79 - s; if (wlo < 0) wlo = 0;
        int whi = 159 - s; if (whi > 80) whi = 80;
        float num = 0.f, nx2 = 0.f;
        const float* xp = src + (s - 79);
        for (int w = wlo; w < whi; ++w) {
            float xv = xp[w];
            num += xv * yr[w];
            nx2 += xv * xv;
        }
        sim[s] = num / (sqrtf(nx2) * ny + 1e-6f);
    }
    __syncthreads();
    int theta = blockArgmax(sim, NSHIFT, fb, ib);
    if (threadIdx.x < IDIM) {
        int i = theta + (int)threadIdx.x - 79;
        yal[threadIdx.x] = ((unsigned)i < 80u) ? src[i] : 0.f;
    }
    __syncthreads();
    return theta;
}

// ---------------- windowed conv encoder ----------------
// H[s][h] = be[h] + sum_{d=0..79} inp[d] * We[(d+80-s)*HDIM + h], s in [0,81)
// returns argmax_s ||H[s]||^2, writes H[ind] into hout.
#define CH 16
__device__ __forceinline__ int encode_fn(const float* __restrict__ We,
                                         const float* __restrict__ be,
                                         const float* inp, float* hout,
                                         float* en, float* psum,
                                         float* fb, int* ib) {
    int tid = threadIdx.x;
    int wid = tid >> 5, lane = tid & 31;
    float bv = be[tid];
    if (tid < NSENC) en[tid] = 0.f;
    __syncthreads();

    for (int s0 = 0; s0 < 80; s0 += CH) {
        float acc[CH];
#pragma unroll
        for (int j = 0; j < CH; j++) acc[j] = 0.f;
        const float* wp = We + (65 - s0) * HDIM + tid;
        int i0 = -15;
        // head: some taps OOB low
        for (; i0 < 0; ++i0) {
            float wv = *wp; wp += HDIM;
#pragma unroll
            for (int j = 0; j < CH; j++) {
                int d = i0 + j;
                if (d >= 0) acc[j] += inp[d] * wv;
            }
        }
        // body: all 16 shifts valid
        for (; i0 < 65; ++i0) {
            float wv = *wp; wp += HDIM;
            const float* xp = inp + i0;
#pragma unroll
            for (int j = 0; j < CH; j++) acc[j] += xp[j] * wv;
        }
        // tail: some taps OOB high
        for (; i0 < 80; ++i0) {
            float wv = *wp; wp += HDIM;
#pragma unroll
            for (int j = 0; j < CH; j++) {
                int d = i0 + j;
                if (d < 80) acc[j] += inp[d] * wv;
            }
        }
        // deterministic energy reduction for the 16 shifts of this chunk
#pragma unroll
        for (int j = 0; j < CH; j++) {
            float val = bv + acc[j];
            float sq = warpSum(val * val);
            if (lane == 0) psum[wid * CH + j] = sq;
        }
        __syncthreads();
        if (tid < CH) {
            float e = 0.f;
#pragma unroll
            for (int w = 0; w < 8; w++) e += psum[w * CH + tid];
            en[s0 + tid] = e;
        }
        __syncthreads();
    }
    // s = 80 (weight rows 0..79)
    {
        float a0 = 0.f, a1 = 0.f, a2 = 0.f, a3 = 0.f;
        const float* wp = We + tid;
#pragma unroll 4
        for (int d = 0; d < 80; d += 4) {
            a0 += inp[d]     * wp[(d)     * HDIM];
            a1 += inp[d + 1] * wp[(d + 1) * HDIM];
            a2 += inp[d + 2] * wp[(d + 2) * HDIM];
            a3 += inp[d + 3] * wp[(d + 3) * HDIM];
        }
        float val = bv + ((a0 + a1) + (a2 + a3));
        float sq = warpSum(val * val);
        if (lane == 0) psum[wid] = sq;
        __syncthreads();
        if (tid == 0) {
            float e = 0.f;
#pragma unroll
            for (int w = 0; w < 8; w++) e += psum[w];
            en[80] = e;
        }
        __syncthreads();
    }
    int ind = blockArgmax(en, NSENC, fb, ib);
    // recompute H[ind]
    {
        float a0 = 0.f, a1 = 0.f, a2 = 0.f, a3 = 0.f;
        const float* wp = We + (80 - ind) * HDIM + tid;
#pragma unroll 4
        for (int d = 0; d < 80; d += 4) {
            a0 += inp[d]     * wp[(d)     * HDIM];
            a1 += inp[d + 1] * wp[(d + 1) * HDIM];
            a2 += inp[d + 2] * wp[(d + 2) * HDIM];
            a3 += inp[d + 3] * wp[(d + 3) * HDIM];
        }
        hout[tid] = bv + ((a0 + a1) + (a2 + a3));
    }
    __syncthreads();
    return ind;
}

// ---------------- HSR (topk energy masking with exclusivity) ----------------
// modifies hbuf and mp in place; returns the hidden loss (0 on first iteration)
__device__ __forceinline__ float hsr_fn(float* hbuf, float* mp, bool first, bool smt,
                                        float* sq, float* wred) {
    int tid = threadIdx.x;
    float h = hbuf[tid];
    sq[tid] = h * h;
    __syncthreads();
    float v = sq[tid];
    int rank = 0;
#pragma unroll 8
    for (int i = 0; i < HDIM; i++) {
        float u = sq[i];
        rank += (u > v || (u == v && i < tid)) ? 1 : 0;
    }
    bool cur = (rank < CDIM);
    float loss = 0.f;
    if (first) {
        mp[tid] = cur ? 1.f : 0.f;
        hbuf[tid] = cur ? h : 0.f;
        __syncthreads();
    } else {
        bool prev = (mp[tid] > 0.f);
        bool inter = prev && cur;
        float lhc = (inter && !smt) ? h * h : 0.f;
        loss = blockSum(lhc, wred);
        float h2 = prev ? 0.f : h;
        __syncthreads();            // done reading sq
        sq[tid] = h2 * h2;
        __syncthreads();
        float v2 = sq[tid];
        int rank2 = 0;
#pragma unroll 8
        for (int i = 0; i < HDIM; i++) {
            float u = sq[i];
            rank2 += (u > v2 || (u == v2 && i < tid)) ? 1 : 0;
        }
        bool cur2 = (rank2 < CDIM);
        if (cur2) mp[tid] += 1.f;
        hbuf[tid] = cur2 ? h2 : 0.f;
        __syncthreads();
    }
    return loss;
}

// ---------------- decode: out[d] = b[ind+d] + sum_h hbuf[h]*W[h*160+ind+d] ----------------
__device__ __forceinline__ void decode_fn(const float* __restrict__ W,
                                          const float* __restrict__ b,
                                          const float* hbuf, int ind, float* out) {
    int d = threadIdx.x;
    if (d < IDIM) {
        float a0 = 0.f, a1 = 0.f, a2 = 0.f, a3 = 0.f;
        const float* wp = W + ind + d;
#pragma unroll 4
        for (int h = 0; h < HDIM; h += 4) {
            float h0 = hbuf[h], h1 = hbuf[h + 1], h2 = hbuf[h + 2], h3 = hbuf[h + 3];
            if (h0 != 0.f) a0 += h0 * wp[(h)     * 160];
            if (h1 != 0.f) a1 += h1 * wp[(h + 1) * 160];
            if (h2 != 0.f) a2 += h2 * wp[(h + 2) * 160];
            if (h3 != 0.f) a3 += h3 * wp[(h + 3) * 160];
        }
        out[d] = b[ind + d] + ((a0 + a1) + (a2 + a3));
    }
    __syncthreads();
}

// ---------------- main per-(b,t) kernel ----------------
__global__ void __launch_bounds__(TPB)
net_main(const float* __restrict__ X, const float* __restrict__ Y,
         const float* __restrict__ We, const float* __restrict__ be,
         const float* __restrict__ Wd, const float* __restrict__ bd,
         const float* __restrict__ Wds, const float* __restrict__ bds) {
    __shared__ float s_x[IDIM], s_y[IDIM], s_yal[IDIM], s_z[IDIM];
    __shared__ float s_xep[IDIM], s_xd[IDIM], s_yd[IDIM];
    __shared__ float s_sim[NSHIFT];
    __shared__ float s_en[NSENC];
    __shared__ float s_h[HDIM];
    __shared__ float s_sq[HDIM];
    __shared__ float s_mps[HDIM];   // mask_prev self
    __shared__ float s_mpr[HDIM];   // mask_prev src
    __shared__ float s_psum[8 * CH];
    __shared__ float s_wred[8];
    __shared__ float s_fb[8];
    __shared__ int   s_ib[8];
    __shared__ unsigned char s_mask[IDIM];

    int tid = threadIdx.x;
    int n = blockIdx.x;

    if (tid < IDIM) {
        s_x[tid] = X[n * IDIM + tid];
        float yv = Y[n * IDIM + tid];
        s_y[tid] = yv;
        s_mask[tid] = (yv == 0.f) ? 1 : 0;
    }
    s_mps[tid] = 0.f;
    s_mpr[tid] = 0.f;
    __syncthreads();

    float cnt = blockSum((tid < IDIM && s_mask[tid]) ? 1.f : 0.f, s_wred);
    bool smt = (cnt > 79.5f);   // seq_mask_t: all features masked

    float loss_total = 0.f;

    for (int it = 0; it < NIT; ++it) {
        // |y_res| used by both alignments this iteration
        float ny2 = blockSum((tid < IDIM) ? s_y[tid] * s_y[tid] : 0.f, s_wred);
        float ny = sqrtf(ny2);

        // ---- alignment 1: x_res vs y_res ----
        int theta1 = align_fn(s_x, s_y, ny, s_sim, s_yal, s_fb, s_ib);

        // ---- attention + reverse shift ----
        float v = (tid < IDIM) ? s_yal[tid] * s_y[tid] : -FLT_MAX;
        float m = blockMax(v, s_wred);
        float e = (tid < IDIM) ? expf(v - m) : 0.f;
        float se = blockSum(e, s_wred);
        if (tid < IDIM) s_z[tid] = s_yal[tid] * (e / se);
        __syncthreads();
        if (tid < IDIM) {
            int i = 79 - theta1 + tid;
            s_xep[tid] = ((unsigned)i < 80u) ? s_z[i] : 0.f;
        }
        __syncthreads();

        // ---- self branch ----
        int ind_self = encode_fn(We, be, s_xep, s_h, s_en, s_psum, s_fb, s_ib);
        float lh_self = hsr_fn(s_h, s_mps, (it == 0), smt, s_sq, s_wred);
        decode_fn(Wds, bds, s_h, ind_self, s_xd);

        int move1 = abs(theta1 - (IDIM - 1));
        float llc = 0.f;
        if (tid < IDIM && move1 <= ETH_I && !s_mask[tid]) {
            float df = s_xd[tid] - s_x[tid];
            llc = (df * df) / ((float)move1 + 1.f);
        }
        float ll_self = blockSum(llc, s_wred);

        // ---- alignment 2: decoded x_ele vs y_res ----
        int theta2 = align_fn(s_xd, s_y, ny, s_sim, s_yal, s_fb, s_ib);

        // ---- src branch ----
        int ind_src = encode_fn(We, be, s_yal, s_h, s_en, s_psum, s_fb, s_ib);
        float lh_src = hsr_fn(s_h, s_mpr, (it == 0), smt, s_sq, s_wred);
        decode_fn(Wd, bd, s_h, ind_src, s_yd);

        int move2 = abs(theta2 - (IDIM - 1));
        llc = 0.f;
        if (tid < IDIM && move2 <= ETH_I && !s_mask[tid]) {
            float df = s_yd[tid] - s_y[tid];
            llc = (df * df) / ((float)move2 + 1.f);
        }
        float ll_src = blockSum(llc, s_wred);

        loss_total += ll_self + ll_src + lh_self + lh_src;

        // ---- residual update ----
        if (tid < IDIM) {
            s_y[tid] -= s_yd[tid];
            s_x[tid] -= s_xd[tid];
        }
        __syncthreads();
    }

    if (tid == 0) g_partial[n] = loss_total;
}

// ---------------- deterministic final reduction ----------------
__global__ void net_reduce(float* __restrict__ out) {
    __shared__ float buf[8];
    float s = 0.f;
    for (int i = threadIdx.x; i < NPOS; i += 256) s += g_partial[i];
    s = warpSum(s);
    int w = threadIdx.x >> 5, l = threadIdx.x & 31;
    if (l == 0) buf[w] = s;
    __syncthreads();
    if (threadIdx.x == 0) {
        float t = 0.f;
#pragma unroll
        for (int i = 0; i < 8; i++) t += buf[i];
        out[0] = t * 0.25f;   // mean over N_ITER = 4 iteration losses
    }
}

extern "C" void kernel_launch(void* const* d_in, const int* in_sizes, int n_in,
                              void* d_out, int out_size) {
    const float* X   = (const float*)d_in[0];
    const float* Y   = (const float*)d_in[1];
    const float* We  = (const float*)d_in[2];
    const float* be  = (const float*)d_in[3];
    const float* Wd  = (const float*)d_in[4];
    const float* bdv = (const float*)d_in[5];
    const float* Wds = (const float*)d_in[6];
    const float* bds = (const float*)d_in[7];
    float* out = (float*)d_out;

    net_main<<<NPOS, TPB>>>(X, Y, We, be, Wd, bdv, Wds, bds);
    net_reduce<<<1, 256>>>(out);
}